// round 1
// baseline (speedup 1.0000x reference)
#include <cuda_runtime.h>
#include <cuda_bf16.h>
#include <cstdint>

#define C_IN   64
#define C_OUT  64
#define KVOL   27
#define PAIRS_PER_BLOCK 32   // 256 threads / 8 threads-per-pair

// ---------------------------------------------------------------------------
// Zero-init the output (d_out is poisoned to 0xAA by the harness).
// ---------------------------------------------------------------------------
__global__ void zero_out_kernel(float4* __restrict__ out, int n4) {
    int i = blockIdx.x * blockDim.x + threadIdx.x;
    if (i < n4) {
        out[i] = make_float4(0.f, 0.f, 0.f, 0.f);
    }
}

// ---------------------------------------------------------------------------
// Sparse conv, gather -> 64x64 GEMM -> scatter-add.
// Grid: (ceil(M/32), 27). Block: 256 threads.
//   - W[k] (64x64 f32 = 16KB) staged in shared memory once per block.
//   - 8 threads cooperate on one pair; each thread owns 8 output channels.
//   - Input row loads are identical within the 8-thread group -> L1 broadcast.
//   - W shared loads are broadcast across the 4 pair-groups of a warp ->
//     8 distinct 16B addresses per LDS.128 = conflict-free.
//   - Scatter via red.global.add.v4.f32 (no return value, 16B granularity).
// ---------------------------------------------------------------------------
__global__ __launch_bounds__(256, 4) void spconv_kernel(
    const float* __restrict__ in_feats,   // [N_IN, 64]
    const float* __restrict__ weights,    // [27, 64, 64]
    const int*   __restrict__ in_map,     // [27, M]
    const int*   __restrict__ out_map,    // [27, M]
    float*       __restrict__ out,        // [N_OUT, 64]
    int M)
{
    __shared__ float4 Wsh[C_IN * C_OUT / 4];   // 1024 float4 = 16 KB

    const int k = blockIdx.y;

    // Stage W[k] into shared memory.
    {
        const float4* Wg = reinterpret_cast<const float4*>(weights + (size_t)k * C_IN * C_OUT);
        #pragma unroll
        for (int i = threadIdx.x; i < C_IN * C_OUT / 4; i += 256) {
            Wsh[i] = Wg[i];
        }
    }
    __syncthreads();

    const int group = threadIdx.x >> 3;          // 0..31 : pair within block
    const int lane8 = threadIdx.x & 7;           // 0..7  : channel-group
    const int jq    = lane8 * 2;                 // float4 column index (2 per thread)

    const int m = blockIdx.x * PAIRS_PER_BLOCK + group;
    if (m >= M) return;

    const int irow = in_map [(size_t)k * M + m];
    const int orow = out_map[(size_t)k * M + m];

    const float4* __restrict__ inrow =
        reinterpret_cast<const float4*>(in_feats + (size_t)irow * C_IN);

    float acc0 = 0.f, acc1 = 0.f, acc2 = 0.f, acc3 = 0.f;
    float acc4 = 0.f, acc5 = 0.f, acc6 = 0.f, acc7 = 0.f;

    #pragma unroll
    for (int i4 = 0; i4 < C_IN / 4; ++i4) {
        const float4 v = __ldg(inrow + i4);
        const int ibase = i4 * 4;

        // i = ibase + 0..3 ; W row i occupies Wsh[i*16 .. i*16+15]
        {
            const float a = v.x;
            const float4 w0 = Wsh[(ibase + 0) * 16 + jq];
            const float4 w1 = Wsh[(ibase + 0) * 16 + jq + 1];
            acc0 += a * w0.x; acc1 += a * w0.y; acc2 += a * w0.z; acc3 += a * w0.w;
            acc4 += a * w1.x; acc5 += a * w1.y; acc6 += a * w1.z; acc7 += a * w1.w;
        }
        {
            const float a = v.y;
            const float4 w0 = Wsh[(ibase + 1) * 16 + jq];
            const float4 w1 = Wsh[(ibase + 1) * 16 + jq + 1];
            acc0 += a * w0.x; acc1 += a * w0.y; acc2 += a * w0.z; acc3 += a * w0.w;
            acc4 += a * w1.x; acc5 += a * w1.y; acc6 += a * w1.z; acc7 += a * w1.w;
        }
        {
            const float a = v.z;
            const float4 w0 = Wsh[(ibase + 2) * 16 + jq];
            const float4 w1 = Wsh[(ibase + 2) * 16 + jq + 1];
            acc0 += a * w0.x; acc1 += a * w0.y; acc2 += a * w0.z; acc3 += a * w0.w;
            acc4 += a * w1.x; acc5 += a * w1.y; acc6 += a * w1.z; acc7 += a * w1.w;
        }
        {
            const float a = v.w;
            const float4 w0 = Wsh[(ibase + 3) * 16 + jq];
            const float4 w1 = Wsh[(ibase + 3) * 16 + jq + 1];
            acc0 += a * w0.x; acc1 += a * w0.y; acc2 += a * w0.z; acc3 += a * w0.w;
            acc4 += a * w1.x; acc5 += a * w1.y; acc6 += a * w1.z; acc7 += a * w1.w;
        }
    }

    // Scatter-add 8 channels (two 16B vector reductions, no return value).
    float* op = out + (size_t)orow * C_OUT + lane8 * 8;
    asm volatile("red.global.add.v4.f32 [%0], {%1, %2, %3, %4};"
                 :: "l"(op), "f"(acc0), "f"(acc1), "f"(acc2), "f"(acc3)
                 : "memory");
    asm volatile("red.global.add.v4.f32 [%0], {%1, %2, %3, %4};"
                 :: "l"(op + 4), "f"(acc4), "f"(acc5), "f"(acc6), "f"(acc7)
                 : "memory");
}

// ---------------------------------------------------------------------------
// Launch contract.
// Inputs (metadata order): in_feats f32 [200000,64], kernel f32 [27,64,64],
//                          in_map i32 [27,M], out_map i32 [27,M]
// Output: f32 [200000,64]
// ---------------------------------------------------------------------------
extern "C" void kernel_launch(void* const* d_in, const int* in_sizes, int n_in,
                              void* d_out, int out_size)
{
    const float* in_feats = (const float*)d_in[0];
    const float* weights  = (const float*)d_in[1];
    const int*   in_map   = (const int*)  d_in[2];
    const int*   out_map  = (const int*)  d_in[3];
    float*       out      = (float*)d_out;

    const int M  = in_sizes[2] / KVOL;
    const int n4 = out_size / 4;

    zero_out_kernel<<<(n4 + 255) / 256, 256>>>((float4*)out, n4);

    dim3 grid((M + PAIRS_PER_BLOCK - 1) / PAIRS_PER_BLOCK, KVOL);
    spconv_kernel<<<grid, 256>>>(in_feats, weights, in_map, out_map, out, M);
}

// round 2
// speedup vs baseline: 3.0569x; 3.0569x over previous
#include <cuda_runtime.h>
#include <cuda_bf16.h>
#include <cstdint>

#define C_IN   64
#define C_OUT  64
#define KVOL   27
#define PAIRS_PER_GROUP 4
#define GROUPS_PER_BLOCK 32                 // 256 threads / 8
#define PAIRS_PER_BLOCK (PAIRS_PER_GROUP * GROUPS_PER_BLOCK)   // 128

// ---------------------------------------------------------------------------
// f32x2 packed helpers (Blackwell dual-fp32 pipe; only reachable via PTX)
// ---------------------------------------------------------------------------
__device__ __forceinline__ uint64_t pack2(float x, float y) {
    uint64_t r;
    asm("mov.b64 %0, {%1, %2};" : "=l"(r) : "f"(x), "f"(y));
    return r;
}
__device__ __forceinline__ void fma2(uint64_t& d, uint64_t a, uint64_t b) {
    asm("fma.rn.f32x2 %0, %1, %2, %0;" : "+l"(d) : "l"(a), "l"(b));
}
__device__ __forceinline__ void unpack2(uint64_t v, float& lo, float& hi) {
    asm("mov.b64 {%0, %1}, %2;" : "=f"(lo), "=f"(hi) : "l"(v));
}

// ---------------------------------------------------------------------------
// Zero-init the output (d_out is poisoned to 0xAA by the harness).
// ---------------------------------------------------------------------------
__global__ void zero_out_kernel(float4* __restrict__ out, int n4) {
    int i = blockIdx.x * blockDim.x + threadIdx.x;
    if (i < n4) out[i] = make_float4(0.f, 0.f, 0.f, 0.f);
}

// ---------------------------------------------------------------------------
// Sparse conv: gather -> 64x64 GEMM -> scatter-add.
// Grid: (ceil(M/128), 27). Block: 256 threads = 32 groups of 8 threads.
// Each group handles 4 pairs; each thread owns 8 output channels per pair.
// W[k] staged in shared; every W read is amortized over the 4 pairs.
// FMAs use packed fma.rn.f32x2 (2 fp32 FMA/instr).
// ---------------------------------------------------------------------------
__global__ __launch_bounds__(256) void spconv_kernel(
    const float* __restrict__ in_feats,   // [N_IN, 64]
    const float* __restrict__ weights,    // [27, 64, 64]
    const int*   __restrict__ in_map,     // [27, M]
    const int*   __restrict__ out_map,    // [27, M]
    float*       __restrict__ out,        // [N_OUT, 64]
    int M)
{
    // Wsh[i*16 + c4] = 16B chunk {col 4c4 .. 4c4+3} of W row i,
    // stored as two packed f32x2 (low = cols {0,1}, high = cols {2,3}).
    __shared__ ulonglong2 Wsh[C_IN * C_OUT / 4];   // 16 KB

    const int k = blockIdx.y;

    {
        const float4* Wg = reinterpret_cast<const float4*>(weights + (size_t)k * C_IN * C_OUT);
        float4* Ws = reinterpret_cast<float4*>(Wsh);
        #pragma unroll
        for (int i = threadIdx.x; i < C_IN * C_OUT / 4; i += 256) {
            Ws[i] = Wg[i];
        }
    }
    __syncthreads();

    const int group = threadIdx.x >> 3;     // 0..31
    const int lane8 = threadIdx.x & 7;      // 0..7 : owns channels [lane8*8, lane8*8+8)
    const int m0 = blockIdx.x * PAIRS_PER_BLOCK + group * PAIRS_PER_GROUP;

    // Load input-row indices for the 4 pairs (clamped; invalid pairs skip RED).
    int  irow[PAIRS_PER_GROUP];
    bool valid[PAIRS_PER_GROUP];
    #pragma unroll
    for (int p = 0; p < PAIRS_PER_GROUP; ++p) {
        const int m = m0 + p;
        valid[p] = (m < M);
        irow[p]  = valid[p] ? __ldg(in_map + (size_t)k * M + m) : 0;
    }

    const float4* __restrict__ inrow[PAIRS_PER_GROUP];
    #pragma unroll
    for (int p = 0; p < PAIRS_PER_GROUP; ++p)
        inrow[p] = reinterpret_cast<const float4*>(in_feats + (size_t)irow[p] * C_IN);

    // acc[p][q] : packed f32x2 pair of output channels (lane8*8 + 2q, +2q+1)
    uint64_t acc[PAIRS_PER_GROUP][4];
    #pragma unroll
    for (int p = 0; p < PAIRS_PER_GROUP; ++p)
        #pragma unroll
        for (int q = 0; q < 4; ++q) acc[p][q] = 0ull;

    #pragma unroll 4
    for (int i4 = 0; i4 < C_IN / 4; ++i4) {
        float4 v[PAIRS_PER_GROUP];
        #pragma unroll
        for (int p = 0; p < PAIRS_PER_GROUP; ++p)
            v[p] = __ldg(inrow[p] + i4);

        #pragma unroll
        for (int ii = 0; ii < 4; ++ii) {
            const int i = i4 * 4 + ii;
            const ulonglong2 w0 = Wsh[i * 16 + lane8 * 2];      // cols lane8*8 .. +3
            const ulonglong2 w1 = Wsh[i * 16 + lane8 * 2 + 1];  // cols lane8*8+4 .. +7

            #pragma unroll
            for (int p = 0; p < PAIRS_PER_GROUP; ++p) {
                const float a = (ii == 0) ? v[p].x : (ii == 1) ? v[p].y
                              : (ii == 2) ? v[p].z : v[p].w;
                const uint64_t aa = pack2(a, a);
                fma2(acc[p][0], aa, w0.x);
                fma2(acc[p][1], aa, w0.y);
                fma2(acc[p][2], aa, w1.x);
                fma2(acc[p][3], aa, w1.y);
            }
        }
    }

    // Scatter-add: per pair, this thread reduces its 8 channels (2x RED.128).
    #pragma unroll
    for (int p = 0; p < PAIRS_PER_GROUP; ++p) {
        if (!valid[p]) continue;
        const int m = m0 + p;
        const int orow = __ldg(out_map + (size_t)k * M + m);
        float* op = out + (size_t)orow * C_OUT + lane8 * 8;

        float c0, c1, c2, c3, c4, c5, c6, c7;
        unpack2(acc[p][0], c0, c1);
        unpack2(acc[p][1], c2, c3);
        unpack2(acc[p][2], c4, c5);
        unpack2(acc[p][3], c6, c7);

        asm volatile("red.global.add.v4.f32 [%0], {%1, %2, %3, %4};"
                     :: "l"(op), "f"(c0), "f"(c1), "f"(c2), "f"(c3) : "memory");
        asm volatile("red.global.add.v4.f32 [%0], {%1, %2, %3, %4};"
                     :: "l"(op + 4), "f"(c4), "f"(c5), "f"(c6), "f"(c7) : "memory");
    }
}

// ---------------------------------------------------------------------------
// Launch contract.
// Inputs: in_feats f32 [200000,64], kernel f32 [27,64,64],
//         in_map i32 [27,M], out_map i32 [27,M].  Output: f32 [200000,64]
// ---------------------------------------------------------------------------
extern "C" void kernel_launch(void* const* d_in, const int* in_sizes, int n_in,
                              void* d_out, int out_size)
{
    const float* in_feats = (const float*)d_in[0];
    const float* weights  = (const float*)d_in[1];
    const int*   in_map   = (const int*)  d_in[2];
    const int*   out_map  = (const int*)  d_in[3];
    float*       out      = (float*)d_out;

    const int M  = in_sizes[2] / KVOL;
    const int n4 = out_size / 4;

    zero_out_kernel<<<(n4 + 255) / 256, 256>>>((float4*)out, n4);

    dim3 grid((M + PAIRS_PER_BLOCK - 1) / PAIRS_PER_BLOCK, KVOL);
    spconv_kernel<<<grid, 256>>>(in_feats, weights, in_map, out_map, out, M);
}

// round 4
// speedup vs baseline: 5.4617x; 1.7867x over previous
#include <cuda_runtime.h>
#include <cuda_bf16.h>
#include <cstdint>

#define KVOL   27
#define C      64
#define TILE_M 128

// ---------------------------------------------------------------------------
// Pre-swizzled bf16 B tiles (hi/lo Dekker split of W^T), 8 KB per offset k.
// Layout: Bt[n][c] K-major, 128B rows, SW128-swizzled bytes.
// ---------------------------------------------------------------------------
__device__ __align__(1024) uint8_t g_Bhi[KVOL * 8192];
__device__ __align__(1024) uint8_t g_Blo[KVOL * 8192];

// ---------------------------------------------------------------------------
// helpers
// ---------------------------------------------------------------------------
static __device__ __forceinline__ uint32_t swz128(uint32_t off) {
    return off ^ ((off >> 3) & 0x70);
}
// pack two floats to bf16x2: e0 -> low half, e1 -> high half
static __device__ __forceinline__ uint32_t pack_bf16x2(float e0, float e1) {
    uint32_t r;
    asm("cvt.rn.bf16x2.f32 %0, %1, %2;" : "=r"(r) : "f"(e1), "f"(e0));
    return r;
}
static __device__ __forceinline__ float bf_lo_f(uint32_t p) { return __uint_as_float(p << 16); }
static __device__ __forceinline__ float bf_hi_f(uint32_t p) { return __uint_as_float(p & 0xFFFF0000u); }

static __device__ __forceinline__ uint32_t smem_u32(const void* p) {
    uint32_t a;
    asm("{ .reg .u64 t; cvta.to.shared.u64 t, %1; cvt.u32.u64 %0, t; }" : "=r"(a) : "l"(p));
    return a;
}
static __device__ __forceinline__ void ldsm4(uint32_t* r, uint32_t addr) {
    asm volatile("ldmatrix.sync.aligned.m8n8.x4.shared.b16 {%0,%1,%2,%3}, [%4];"
                 : "=r"(r[0]), "=r"(r[1]), "=r"(r[2]), "=r"(r[3]) : "r"(addr));
}
static __device__ __forceinline__ void mma_bf16(float* d, const uint32_t* a,
                                                uint32_t b0, uint32_t b1) {
    asm volatile(
        "mma.sync.aligned.m16n8k16.row.col.f32.bf16.bf16.f32 "
        "{%0,%1,%2,%3}, {%4,%5,%6,%7}, {%8,%9}, {%0,%1,%2,%3};"
        : "+f"(d[0]), "+f"(d[1]), "+f"(d[2]), "+f"(d[3])
        : "r"(a[0]), "r"(a[1]), "r"(a[2]), "r"(a[3]), "r"(b0), "r"(b1));
}

// ---------------------------------------------------------------------------
// Zero-init output
// ---------------------------------------------------------------------------
__global__ void zero_out_kernel(float4* __restrict__ out, int n4) {
    int i = blockIdx.x * blockDim.x + threadIdx.x;
    if (i < n4) out[i] = make_float4(0.f, 0.f, 0.f, 0.f);
}

// ---------------------------------------------------------------------------
// prep_B: W[k][c][n] -> Bt[n][c] bf16 hi/lo, SW128 pre-swizzled.
// Grid: 27 x 256. Thread t: n = t>>2, cq = t&3 -> 16 c-values.
// ---------------------------------------------------------------------------
__global__ void prep_B(const float* __restrict__ weights) {
    const int k  = blockIdx.x;
    const int t  = threadIdx.x;
    const int n  = t >> 2;
    const int cq = t & 3;

    uint32_t hi[8], lo[8];
    #pragma unroll
    for (int jp = 0; jp < 8; ++jp) {
        const int c0 = cq * 16 + jp * 2;
        const float w0 = weights[(size_t)(k * C + c0) * C + n];
        const float w1 = weights[(size_t)(k * C + c0 + 1) * C + n];
        const uint32_t h = pack_bf16x2(w0, w1);
        hi[jp] = h;
        lo[jp] = pack_bf16x2(w0 - bf_lo_f(h), w1 - bf_hi_f(h));
    }
    const uint32_t base = (uint32_t)n * 128 + cq * 32;
    const uint32_t s0 = swz128(base);
    const uint32_t s1 = swz128(base + 16);
    *(uint4*)(g_Bhi + (size_t)k * 8192 + s0) = make_uint4(hi[0], hi[1], hi[2], hi[3]);
    *(uint4*)(g_Bhi + (size_t)k * 8192 + s1) = make_uint4(hi[4], hi[5], hi[6], hi[7]);
    *(uint4*)(g_Blo + (size_t)k * 8192 + s0) = make_uint4(lo[0], lo[1], lo[2], lo[3]);
    *(uint4*)(g_Blo + (size_t)k * 8192 + s1) = make_uint4(lo[4], lo[5], lo[6], lo[7]);
}

// ---------------------------------------------------------------------------
// Main kernel: 1 block = (k, 128-row tile). 256 threads = 8 warps.
// Warp w computes rows [16w, 16w+16) x all 64 cols via mma.sync bf16 3-term.
// SMEM (static, exactly 48 KB): A_hi 16K | A_lo 16K | B_hi 8K | B_lo 8K.
// ---------------------------------------------------------------------------
#define OFF_AHI 0
#define OFF_ALO 16384
#define OFF_BHI 32768
#define OFF_BLO 40960

__global__ __launch_bounds__(256, 2) void spconv_mma_kernel(
    const float* __restrict__ in_feats,   // [N_IN, 64]
    const int*   __restrict__ in_map,     // [27, M]
    const int*   __restrict__ out_map,    // [27, M]
    float*       __restrict__ out,        // [N_OUT, 64]
    int M)
{
    __shared__ __align__(1024) uint8_t smem[49152];
    const uint32_t sb = smem_u32(smem);

    const int tid = threadIdx.x;
    const int wid = tid >> 5;
    const int lid = tid & 31;
    const int k   = blockIdx.y;
    const int m0  = blockIdx.x * TILE_M;

    // ---- stage B tiles (pre-swizzled; linear 16 KB copy) ----
    {
        const uint4* bh = (const uint4*)(g_Bhi + (size_t)k * 8192);
        const uint4* bl = (const uint4*)(g_Blo + (size_t)k * 8192);
        uint4* sh = (uint4*)(smem + OFF_BHI);
        uint4* sl = (uint4*)(smem + OFF_BLO);
        #pragma unroll
        for (int i = 0; i < 2; ++i) {
            const int idx = tid + i * 256;
            sh[idx] = __ldg(bh + idx);
            sl[idx] = __ldg(bl + idx);
        }
    }

    // ---- gather + bf16 hi/lo split of A (2 threads per row) ----
    {
        const int r    = tid >> 1;
        const int half = tid & 1;
        const int m    = m0 + r;
        const int irow = (m < M) ? __ldg(in_map + (size_t)k * M + m) : 0;
        const float4* src = (const float4*)(in_feats + (size_t)irow * C) + half * 8;

        uint32_t hi[16], lo[16];
        #pragma unroll
        for (int j = 0; j < 8; ++j) {
            const float4 v = __ldg(src + j);
            const uint32_t h0 = pack_bf16x2(v.x, v.y);
            const uint32_t h1 = pack_bf16x2(v.z, v.w);
            hi[2 * j]     = h0;
            hi[2 * j + 1] = h1;
            lo[2 * j]     = pack_bf16x2(v.x - bf_lo_f(h0), v.y - bf_hi_f(h0));
            lo[2 * j + 1] = pack_bf16x2(v.z - bf_lo_f(h1), v.w - bf_hi_f(h1));
        }
        const uint32_t base = (uint32_t)r * 128 + half * 64;
        #pragma unroll
        for (int q = 0; q < 4; ++q) {
            const uint32_t sw = swz128(base + q * 16);
            *(uint4*)(smem + OFF_AHI + sw) = make_uint4(hi[4*q], hi[4*q+1], hi[4*q+2], hi[4*q+3]);
            *(uint4*)(smem + OFF_ALO + sw) = make_uint4(lo[4*q], lo[4*q+1], lo[4*q+2], lo[4*q+3]);
        }
    }
    __syncthreads();

    // ---- compute: 96 mma per warp ----
    const int rbase = wid * 16;
    const int lmat  = lid >> 3;   // which 8x8 matrix this lane addresses
    const int lrow  = lid & 7;

    // A: row-half = lmat&1, k-half = lmat>>1
    const uint32_t a_row = rbase + ((lmat & 1) << 3) + lrow;
    const uint32_t a_kh  = (uint32_t)(lmat >> 1) << 4;
    // B: n-half = lmat>>1, k-half = lmat&1
    const uint32_t b_nrow = ((lmat >> 1) << 3) + lrow;
    const uint32_t b_kh   = (uint32_t)(lmat & 1) << 4;

    float acc[8][4];
    #pragma unroll
    for (int j = 0; j < 8; ++j)
        #pragma unroll
        for (int i = 0; i < 4; ++i) acc[j][i] = 0.f;

    #pragma unroll
    for (int c = 0; c < 4; ++c) {
        uint32_t aH[4], aL[4];
        const uint32_t abyte = a_row * 128 + c * 32 + a_kh;
        ldsm4(aH, sb + OFF_AHI + swz128(abyte));
        ldsm4(aL, sb + OFF_ALO + swz128(abyte));

        #pragma unroll
        for (int jp = 0; jp < 4; ++jp) {
            const uint32_t n = jp * 16 + b_nrow;
            const uint32_t bbyte = n * 128 + c * 32 + b_kh;
            uint32_t bH[4], bL[4];
            ldsm4(bH, sb + OFF_BHI + swz128(bbyte));
            ldsm4(bL, sb + OFF_BLO + swz128(bbyte));

            mma_bf16(acc[2 * jp],     aH, bH[0], bH[1]);
            mma_bf16(acc[2 * jp],     aH, bL[0], bL[1]);
            mma_bf16(acc[2 * jp],     aL, bH[0], bH[1]);
            mma_bf16(acc[2 * jp + 1], aH, bH[2], bH[3]);
            mma_bf16(acc[2 * jp + 1], aH, bL[2], bL[3]);
            mma_bf16(acc[2 * jp + 1], aL, bH[2], bH[3]);
        }
    }

    // ---- scatter from fragments: lane owns rows rbase+lid/4 and +8 ----
    {
        const int qrow = lid >> 2;
        const int qcol = (lid & 3) * 2;

        const int mA = m0 + rbase + qrow;
        if (mA < M) {
            const int orow = __ldg(out_map + (size_t)k * M + mA);
            float* op = out + (size_t)orow * C + qcol;
            #pragma unroll
            for (int j = 0; j < 8; ++j) {
                asm volatile("red.global.add.v2.f32 [%0], {%1, %2};"
                             :: "l"(op + j * 8), "f"(acc[j][0]), "f"(acc[j][1]) : "memory");
            }
        }
        const int mB = mA + 8;
        if (mB < M) {
            const int orow = __ldg(out_map + (size_t)k * M + mB);
            float* op = out + (size_t)orow * C + qcol;
            #pragma unroll
            for (int j = 0; j < 8; ++j) {
                asm volatile("red.global.add.v2.f32 [%0], {%1, %2};"
                             :: "l"(op + j * 8), "f"(acc[j][2]), "f"(acc[j][3]) : "memory");
            }
        }
    }
}

// ---------------------------------------------------------------------------
// Launch
// ---------------------------------------------------------------------------
extern "C" void kernel_launch(void* const* d_in, const int* in_sizes, int n_in,
                              void* d_out, int out_size)
{
    const float* in_feats = (const float*)d_in[0];
    const float* weights  = (const float*)d_in[1];
    const int*   in_map   = (const int*)  d_in[2];
    const int*   out_map  = (const int*)  d_in[3];
    float*       out      = (float*)d_out;

    const int M  = in_sizes[2] / KVOL;
    const int n4 = out_size / 4;

    zero_out_kernel<<<(n4 + 255) / 256, 256>>>((float4*)out, n4);
    prep_B<<<KVOL, 256>>>(weights);

    dim3 grid((M + TILE_M - 1) / TILE_M, KVOL);
    spconv_mma_kernel<<<grid, 256>>>(in_feats, in_map, out_map, out, M);
}

// round 5
// speedup vs baseline: 6.4842x; 1.1872x over previous
#include <cuda_runtime.h>
#include <cuda_bf16.h>
#include <cstdint>

#define KVOL   27
#define C      64
#define TILE_M 256

// ---------------------------------------------------------------------------
// Pre-swizzled bf16 B tiles (hi/lo Dekker split of W^T), 8 KB per offset k.
// ---------------------------------------------------------------------------
__device__ __align__(1024) uint8_t g_Bhi[KVOL * 8192];
__device__ __align__(1024) uint8_t g_Blo[KVOL * 8192];

// ---------------------------------------------------------------------------
// helpers
// ---------------------------------------------------------------------------
static __device__ __forceinline__ uint32_t swz128(uint32_t off) {
    return off ^ ((off >> 3) & 0x70);
}
static __device__ __forceinline__ uint32_t pack_bf16x2(float e0, float e1) {
    uint32_t r;
    asm("cvt.rn.bf16x2.f32 %0, %1, %2;" : "=r"(r) : "f"(e1), "f"(e0));
    return r;
}
static __device__ __forceinline__ float bf_lo_f(uint32_t p) { return __uint_as_float(p << 16); }
static __device__ __forceinline__ float bf_hi_f(uint32_t p) { return __uint_as_float(p & 0xFFFF0000u); }

static __device__ __forceinline__ uint32_t smem_u32(const void* p) {
    uint32_t a;
    asm("{ .reg .u64 t; cvta.to.shared.u64 t, %1; cvt.u32.u64 %0, t; }" : "=r"(a) : "l"(p));
    return a;
}
static __device__ __forceinline__ void ldsm4(uint32_t* r, uint32_t addr) {
    asm volatile("ldmatrix.sync.aligned.m8n8.x4.shared.b16 {%0,%1,%2,%3}, [%4];"
                 : "=r"(r[0]), "=r"(r[1]), "=r"(r[2]), "=r"(r[3]) : "r"(addr));
}
static __device__ __forceinline__ void mma_bf16(float* d, const uint32_t* a,
                                                uint32_t b0, uint32_t b1) {
    asm volatile(
        "mma.sync.aligned.m16n8k16.row.col.f32.bf16.bf16.f32 "
        "{%0,%1,%2,%3}, {%4,%5,%6,%7}, {%8,%9}, {%0,%1,%2,%3};"
        : "+f"(d[0]), "+f"(d[1]), "+f"(d[2]), "+f"(d[3])
        : "r"(a[0]), "r"(a[1]), "r"(a[2]), "r"(a[3]), "r"(b0), "r"(b1));
}
static __device__ __forceinline__ void cp_async16(uint32_t saddr, const void* gptr) {
    asm volatile("cp.async.cg.shared.global [%0], [%1], 16;" :: "r"(saddr), "l"(gptr));
}

// ---------------------------------------------------------------------------
// Zero-init output
// ---------------------------------------------------------------------------
__global__ void zero_out_kernel(float4* __restrict__ out, int n4) {
    int i = blockIdx.x * blockDim.x + threadIdx.x;
    if (i < n4) out[i] = make_float4(0.f, 0.f, 0.f, 0.f);
}

// ---------------------------------------------------------------------------
// prep_B: W[k][c][n] -> Bt[n][c] bf16 hi/lo, SW128 pre-swizzled.
// ---------------------------------------------------------------------------
__global__ void prep_B(const float* __restrict__ weights) {
    const int k  = blockIdx.x;
    const int t  = threadIdx.x;
    const int n  = t >> 2;
    const int cq = t & 3;

    uint32_t hi[8], lo[8];
    #pragma unroll
    for (int jp = 0; jp < 8; ++jp) {
        const int c0 = cq * 16 + jp * 2;
        const float w0 = weights[(size_t)(k * C + c0) * C + n];
        const float w1 = weights[(size_t)(k * C + c0 + 1) * C + n];
        const uint32_t h = pack_bf16x2(w0, w1);
        hi[jp] = h;
        lo[jp] = pack_bf16x2(w0 - bf_lo_f(h), w1 - bf_hi_f(h));
    }
    const uint32_t base = (uint32_t)n * 128 + cq * 32;
    const uint32_t s0 = swz128(base);
    const uint32_t s1 = swz128(base + 16);
    *(uint4*)(g_Bhi + (size_t)k * 8192 + s0) = make_uint4(hi[0], hi[1], hi[2], hi[3]);
    *(uint4*)(g_Bhi + (size_t)k * 8192 + s1) = make_uint4(hi[4], hi[5], hi[6], hi[7]);
    *(uint4*)(g_Blo + (size_t)k * 8192 + s0) = make_uint4(lo[0], lo[1], lo[2], lo[3]);
    *(uint4*)(g_Blo + (size_t)k * 8192 + s1) = make_uint4(lo[4], lo[5], lo[6], lo[7]);
}

// ---------------------------------------------------------------------------
// Main kernel: 1 block = (k, 256-row tile). 256 threads = 8 warps.
// Each warp computes 32 rows x 64 cols (bf16 3-term mma.sync).
// SMEM dynamic 80 KB: A_hi 32K | A_lo 32K | B_hi 8K | B_lo 8K.
// ---------------------------------------------------------------------------
#define OFF_AHI 0
#define OFF_ALO 32768
#define OFF_BHI 65536
#define OFF_BLO 73728
#define SMEM_TOTAL 81920

__global__ __launch_bounds__(256, 2) void spconv_mma_kernel(
    const float* __restrict__ in_feats,   // [N_IN, 64]
    const int*   __restrict__ in_map,     // [27, M]
    const int*   __restrict__ out_map,    // [27, M]
    float*       __restrict__ out,        // [N_OUT, 64]
    int M)
{
    extern __shared__ __align__(1024) uint8_t smem[];
    const uint32_t sb = smem_u32(smem);

    const int tid = threadIdx.x;
    const int wid = tid >> 5;
    const int lid = tid & 31;
    const int k   = blockIdx.y;
    const int m0  = blockIdx.x * TILE_M;

    // ---- B tiles via cp.async (pre-swizzled; linear 16 KB), overlapped with gather
    {
        const uint4* bh = (const uint4*)(g_Bhi + (size_t)k * 8192);
        const uint4* bl = (const uint4*)(g_Blo + (size_t)k * 8192);
        #pragma unroll
        for (int i = 0; i < 2; ++i) {
            const int idx = tid + i * 256;
            cp_async16(sb + OFF_BHI + idx * 16, bh + idx);
            cp_async16(sb + OFF_BLO + idx * 16, bl + idx);
        }
        asm volatile("cp.async.commit_group;" ::: "memory");
    }

    // ---- gather + bf16 hi/lo split of A (1 thread per row, 256 rows) ----
    {
        const int r    = tid;
        const int m    = m0 + r;
        const int irow = (m < M) ? __ldg(in_map + (size_t)k * M + m) : 0;
        const float4* src = (const float4*)(in_feats + (size_t)irow * C);
        const uint32_t base = (uint32_t)r * 128;

        #pragma unroll
        for (int q = 0; q < 8; ++q) {
            const float4 v0 = __ldg(src + 2 * q);
            const float4 v1 = __ldg(src + 2 * q + 1);
            const uint32_t h0 = pack_bf16x2(v0.x, v0.y);
            const uint32_t h1 = pack_bf16x2(v0.z, v0.w);
            const uint32_t h2 = pack_bf16x2(v1.x, v1.y);
            const uint32_t h3 = pack_bf16x2(v1.z, v1.w);
            const uint32_t l0 = pack_bf16x2(v0.x - bf_lo_f(h0), v0.y - bf_hi_f(h0));
            const uint32_t l1 = pack_bf16x2(v0.z - bf_lo_f(h1), v0.w - bf_hi_f(h1));
            const uint32_t l2 = pack_bf16x2(v1.x - bf_lo_f(h2), v1.y - bf_hi_f(h2));
            const uint32_t l3 = pack_bf16x2(v1.z - bf_lo_f(h3), v1.w - bf_hi_f(h3));
            const uint32_t sw = swz128(base + q * 16);
            *(uint4*)(smem + OFF_AHI + sw) = make_uint4(h0, h1, h2, h3);
            *(uint4*)(smem + OFF_ALO + sw) = make_uint4(l0, l1, l2, l3);
        }
    }
    asm volatile("cp.async.wait_group 0;" ::: "memory");
    __syncthreads();

    // ---- compute: warp w -> rows [32w, 32w+32), all 64 cols ----
    const int rbase = wid * 32;
    const int lmat  = lid >> 3;
    const int lrow  = lid & 7;

    const uint32_t a_kh   = (uint32_t)(lmat >> 1) << 4;
    const uint32_t a_roff = ((lmat & 1) << 3) + lrow;
    const uint32_t b_nrow = ((lmat >> 1) << 3) + lrow;
    const uint32_t b_kh   = (uint32_t)(lmat & 1) << 4;

    float acc[2][8][4];
    #pragma unroll
    for (int rt = 0; rt < 2; ++rt)
        #pragma unroll
        for (int j = 0; j < 8; ++j)
            #pragma unroll
            for (int i = 0; i < 4; ++i) acc[rt][j][i] = 0.f;

    #pragma unroll
    for (int c = 0; c < 4; ++c) {
        uint32_t aH[2][4], aL[2][4];
        #pragma unroll
        for (int rt = 0; rt < 2; ++rt) {
            const uint32_t abyte = (rbase + rt * 16 + a_roff) * 128 + c * 32 + a_kh;
            ldsm4(aH[rt], sb + OFF_AHI + swz128(abyte));
            ldsm4(aL[rt], sb + OFF_ALO + swz128(abyte));
        }

        #pragma unroll
        for (int jp = 0; jp < 4; ++jp) {
            const uint32_t bbyte = (jp * 16 + b_nrow) * 128 + c * 32 + b_kh;
            uint32_t bH[4], bL[4];
            ldsm4(bH, sb + OFF_BHI + swz128(bbyte));
            ldsm4(bL, sb + OFF_BLO + swz128(bbyte));

            #pragma unroll
            for (int rt = 0; rt < 2; ++rt) {
                mma_bf16(acc[rt][2 * jp],     aH[rt], bH[0], bH[1]);
                mma_bf16(acc[rt][2 * jp],     aH[rt], bL[0], bL[1]);
                mma_bf16(acc[rt][2 * jp],     aL[rt], bH[0], bH[1]);
                mma_bf16(acc[rt][2 * jp + 1], aH[rt], bH[2], bH[3]);
                mma_bf16(acc[rt][2 * jp + 1], aH[rt], bL[2], bL[3]);
                mma_bf16(acc[rt][2 * jp + 1], aL[rt], bH[2], bH[3]);
            }
        }
    }

    // ---- scatter: lane-pair shfl merge -> red.global.add.v4.f32 ----
    // Even lane emits v4 for row (qrow), odd lane for row (qrow+8).
    {
        const int odd  = lid & 1;
        const int qrow = lid >> 2;
        const int colA = (lid & 3) * 2 - (odd ? 2 : 0);   // 4-aligned column base

        #pragma unroll
        for (int rt = 0; rt < 2; ++rt) {
            const int rowLocal = rbase + rt * 16 + qrow + (odd ? 8 : 0);
            const int m = m0 + rowLocal;
            const bool v = (m < M);
            const int orow = v ? __ldg(out_map + (size_t)k * M + m) : 0;
            float* op = out + (size_t)orow * C + colA;

            #pragma unroll
            for (int jp = 0; jp < 8; ++jp) {
                const float d0 = acc[rt][jp][0], d1 = acc[rt][jp][1];
                const float d2 = acc[rt][jp][2], d3 = acc[rt][jp][3];
                unsigned long long snd;
                asm("mov.b64 %0, {%1, %2};" : "=l"(snd)
                    : "f"(odd ? d0 : d2), "f"(odd ? d1 : d3));
                const unsigned long long rcv = __shfl_xor_sync(0xffffffffu, snd, 1);
                float r0, r1;
                asm("mov.b64 {%0, %1}, %2;" : "=f"(r0), "=f"(r1) : "l"(rcv));

                const float e0 = odd ? r0 : d0;
                const float e1 = odd ? r1 : d1;
                const float e2 = odd ? d2 : r0;
                const float e3 = odd ? d3 : r1;
                if (v) {
                    asm volatile("red.global.add.v4.f32 [%0], {%1, %2, %3, %4};"
                                 :: "l"(op + jp * 8),
                                    "f"(e0), "f"(e1), "f"(e2), "f"(e3) : "memory");
                }
            }
        }
    }
}

// ---------------------------------------------------------------------------
// Launch
// ---------------------------------------------------------------------------
extern "C" void kernel_launch(void* const* d_in, const int* in_sizes, int n_in,
                              void* d_out, int out_size)
{
    const float* in_feats = (const float*)d_in[0];
    const float* weights  = (const float*)d_in[1];
    const int*   in_map   = (const int*)  d_in[2];
    const int*   out_map  = (const int*)  d_in[3];
    float*       out      = (float*)d_out;

    const int M  = in_sizes[2] / KVOL;
    const int n4 = out_size / 4;

    static bool attr_set = false;
    if (!attr_set) {
        cudaFuncSetAttribute(spconv_mma_kernel,
                             cudaFuncAttributeMaxDynamicSharedMemorySize, SMEM_TOTAL);
        attr_set = true;
    }

    zero_out_kernel<<<(n4 + 255) / 256, 256>>>((float4*)out, n4);
    prep_B<<<KVOL, 256>>>(weights);

    dim3 grid((M + TILE_M - 1) / TILE_M, KVOL);
    spconv_mma_kernel<<<grid, 256, SMEM_TOTAL>>>(in_feats, in_map, out_map, out, M);
}